// round 12
// baseline (speedup 1.0000x reference)
#include <cuda_runtime.h>
#include <cuda_bf16.h>
#include <cuda_fp16.h>
#include <cstdint>
#include <math.h>

#define DIM      128
#define HEADS    8
#define NMAX     100000
#define EMAX     1600000
#define SCAN_BLK 1024
#define MAX_BLKS ((NMAX + SCAN_BLK - 1) / SCAN_BLK + 2)

// ---------------- device scratch (allocation-free rule) ----------------
__device__ __half g_nth[(size_t)NMAX * DIM]; // transformed node features (fp16)
__device__ float g_es[(size_t)NMAX * HEADS]; // exp(sender score)
__device__ int   g_cnt[NMAX];                // in-degree counts (kept zeroed)
__device__ int   g_row[NMAX + 1];            // CSR row offsets
__device__ int   g_pos[EMAX];                // per-edge slot within its segment
__device__ int   g_csr[EMAX];                // CSR payload: sender ids
__device__ int   g_bsum[MAX_BLKS];           // scan block sums
// W as bf16 hi/lo images, layout Bt[n][k] row-major with ldmatrix swizzle
__device__ __align__(16) char g_Bhi[32768];
__device__ __align__(16) char g_Blo[32768];

__device__ __forceinline__ float lrelu(float x) { return x > 0.0f ? x : 0.2f * x; }

__device__ __forceinline__ uint32_t smem_u32(const void* p) {
    uint32_t a;
    asm("{ .reg .u64 t; cvta.to.shared.u64 t, %1; cvt.u32.u64 %0, t; }" : "=r"(a) : "l"(p));
    return a;
}

// swizzled byte offset inside a [rows][128 bf16] tile (256B rows)
__device__ __forceinline__ uint32_t toff(int row, int k) {
    return (uint32_t)(row * 256 + ((((k >> 3) ^ (row & 7)) & 15) << 4) + ((k & 7) << 1));
}

#define LDSM4(r, addr) asm volatile( \
    "ldmatrix.sync.aligned.m8n8.x4.shared.b16 {%0,%1,%2,%3}, [%4];" \
    : "=r"((r)[0]), "=r"((r)[1]), "=r"((r)[2]), "=r"((r)[3]) : "r"(addr))
#define LDSM2(r, addr) asm volatile( \
    "ldmatrix.sync.aligned.m8n8.x2.shared.b16 {%0,%1}, [%2];" \
    : "=r"((r)[0]), "=r"((r)[1]) : "r"(addr))
#define MMA(c, a, b) asm volatile( \
    "mma.sync.aligned.m16n8k16.row.col.f32.bf16.bf16.f32 " \
    "{%0,%1,%2,%3},{%4,%5,%6,%7},{%8,%9},{%0,%1,%2,%3};" \
    : "+f"((c)[0]), "+f"((c)[1]), "+f"((c)[2]), "+f"((c)[3]) \
    : "r"((a)[0]), "r"((a)[1]), "r"((a)[2]), "r"((a)[3]), "r"((b)[0]), "r"((b)[1]))

// ---------------------------------------------------------------------------
// prep: W (fp32 [k][n]) -> bf16 hi/lo Bt[n][k] swizzled images (once, global)
// ---------------------------------------------------------------------------
__global__ void prep_w_kernel(const float* __restrict__ W) {
    int t = blockIdx.x * blockDim.x + threadIdx.x;
    if (t >= DIM * DIM) return;
    int k = t >> 7, n = t & 127;
    float x = W[k * DIM + n];
    __nv_bfloat16 h = __float2bfloat16(x);
    __nv_bfloat16 l = __float2bfloat16(x - __bfloat162float(h));
    uint32_t so = toff(n, k);
    *reinterpret_cast<__nv_bfloat16*>(g_Bhi + so) = h;
    *reinterpret_cast<__nv_bfloat16*>(g_Blo + so) = l;
}

// ---------------------------------------------------------------------------
// GEMM: bf16-split mma.sync, 128-row tiles. Epilogue: +bias, store nt (fp16),
// fused per-head score -> g_es = exp(score).
// ---------------------------------------------------------------------------
#define SM_AHI 0
#define SM_ALO 32768
#define SM_BHI 65536
#define SM_BLO 98304
#define SM_TOTAL 131072

__global__ __launch_bounds__(256, 1)
void gemm_mma_kernel(const float* __restrict__ A, const float* __restrict__ bias,
                     const float* __restrict__ attn_w, int N) {
    extern __shared__ __align__(1024) char smem[];
    const uint32_t sb = smem_u32(smem);
    const int tid = threadIdx.x;
    const int wid = tid >> 5;
    const int lane = tid & 31;
    const int row0 = blockIdx.x * 128;

    {
        const int4* shi = reinterpret_cast<const int4*>(g_Bhi);
        const int4* slo = reinterpret_cast<const int4*>(g_Blo);
        int4* dhi = reinterpret_cast<int4*>(smem + SM_BHI);
        int4* dlo = reinterpret_cast<int4*>(smem + SM_BLO);
        for (int i = tid; i < 2048; i += 256) { dhi[i] = shi[i]; dlo[i] = slo[i]; }
    }
    for (int i = 0; i < 16; i++) {
        int idx4 = tid + i * 256;
        int r = idx4 >> 5;
        int c4 = (idx4 & 31) * 4;
        float4 v = make_float4(0.f, 0.f, 0.f, 0.f);
        if (row0 + r < N)
            v = *reinterpret_cast<const float4*>(&A[(size_t)(row0 + r) * DIM + c4]);
        float xs[4] = {v.x, v.y, v.z, v.w};
        __nv_bfloat16 hs[4], ls[4];
#pragma unroll
        for (int j = 0; j < 4; j++) {
            hs[j] = __float2bfloat16(xs[j]);
            ls[j] = __float2bfloat16(xs[j] - __bfloat162float(hs[j]));
        }
        uint32_t so = toff(r, c4);
        *reinterpret_cast<__nv_bfloat162*>(smem + SM_AHI + so)     = __halves2bfloat162(hs[0], hs[1]);
        *reinterpret_cast<__nv_bfloat162*>(smem + SM_AHI + so + 4) = __halves2bfloat162(hs[2], hs[3]);
        *reinterpret_cast<__nv_bfloat162*>(smem + SM_ALO + so)     = __halves2bfloat162(ls[0], ls[1]);
        *reinterpret_cast<__nv_bfloat162*>(smem + SM_ALO + so + 4) = __halves2bfloat162(ls[2], ls[3]);
    }
    __syncthreads();

    const int wm = wid >> 2;
    const int wn = wid & 3;
    const int r_base = wm * 64;
    const int n_base = wn * 32;

    float acc[4][4][4];
#pragma unroll
    for (int mi = 0; mi < 4; mi++)
#pragma unroll
        for (int ni = 0; ni < 4; ni++)
#pragma unroll
            for (int q = 0; q < 4; q++) acc[mi][ni][q] = 0.0f;

    const int L = lane & 15;
#pragma unroll
    for (int ks = 0; ks < 8; ks++) {
        uint32_t ah[4][4], al[4][4], bh[4][2], bl[4][2];
        const int ka = ks * 16 + (lane >> 4) * 8;
        const int kb = ks * 16 + ((L >> 3) & 1) * 8;
#pragma unroll
        for (int mi = 0; mi < 4; mi++) {
            uint32_t off = toff(r_base + mi * 16 + L, ka);
            LDSM4(ah[mi], sb + SM_AHI + off);
            LDSM4(al[mi], sb + SM_ALO + off);
        }
#pragma unroll
        for (int ni = 0; ni < 4; ni++) {
            uint32_t off = toff(n_base + ni * 8 + (L & 7), kb);
            LDSM2(bh[ni], sb + SM_BHI + off);
            LDSM2(bl[ni], sb + SM_BLO + off);
        }
#pragma unroll
        for (int mi = 0; mi < 4; mi++)
#pragma unroll
            for (int ni = 0; ni < 4; ni++) {
                MMA(acc[mi][ni], ah[mi], bh[ni]);
                MMA(acc[mi][ni], ah[mi], bl[ni]);
                MMA(acc[mi][ni], al[mi], bh[ni]);
            }
    }

    // ---- epilogue ----
    float aw[16];
#pragma unroll
    for (int j = 0; j < 16; j++) aw[j] = __ldg(&attn_w[j]);

    float sp[8][2];
#pragma unroll
    for (int q = 0; q < 8; q++) { sp[q][0] = 0.0f; sp[q][1] = 0.0f; }

#pragma unroll
    for (int ni = 0; ni < 4; ni++) {
        int n0 = n_base + ni * 8 + (lane & 3) * 2;
        float bw0 = __ldg(&bias[n0]), bw1 = __ldg(&bias[n0 + 1]);
        float aw0 = aw[n0 & 15], aw1 = aw[(n0 + 1) & 15];
        int hl = ni >> 1;
#pragma unroll
        for (int mi = 0; mi < 4; mi++) {
            float c0 = acc[mi][ni][0] + bw0, c1 = acc[mi][ni][1] + bw1;
            float c2 = acc[mi][ni][2] + bw0, c3 = acc[mi][ni][3] + bw1;
            int ra = row0 + r_base + mi * 16 + (lane >> 2);
            int rb = ra + 8;
            if (ra < N) *reinterpret_cast<__half2*>(&g_nth[(size_t)ra * DIM + n0]) = __floats2half2_rn(c0, c1);
            if (rb < N) *reinterpret_cast<__half2*>(&g_nth[(size_t)rb * DIM + n0]) = __floats2half2_rn(c2, c3);
            sp[mi * 2 + 0][hl] += lrelu(c0) * aw0 + lrelu(c1) * aw1;
            sp[mi * 2 + 1][hl] += lrelu(c2) * aw0 + lrelu(c3) * aw1;
        }
    }
#pragma unroll
    for (int slot = 0; slot < 8; slot++)
#pragma unroll
        for (int hl = 0; hl < 2; hl++) {
            float v = sp[slot][hl];
            v += __shfl_xor_sync(0xffffffffu, v, 1);
            v += __shfl_xor_sync(0xffffffffu, v, 2);
            if ((lane & 3) == 0) {
                int row = row0 + r_base + (slot >> 1) * 16 + (slot & 1) * 8 + (lane >> 2);
                if (row < N) g_es[(size_t)row * HEADS + wn * 2 + hl] = __expf(v);
            }
        }
}

// ---------------------------------------------------------------------------
// CSR build (side stream): count (+slot record) -> scan1 -> scan23 -> fill
// ---------------------------------------------------------------------------
__global__ void count_kernel(const int* __restrict__ receivers, int E) {
    int t = blockIdx.x * blockDim.x + threadIdx.x;
    int e0 = t * 4;
    if (e0 + 3 < E) {
        int4 r = *reinterpret_cast<const int4*>(&receivers[e0]);
        int4 p;
        p.x = atomicAdd(&g_cnt[r.x], 1);
        p.y = atomicAdd(&g_cnt[r.y], 1);
        p.z = atomicAdd(&g_cnt[r.z], 1);
        p.w = atomicAdd(&g_cnt[r.w], 1);
        *reinterpret_cast<int4*>(&g_pos[e0]) = p;
    } else {
        for (int e = e0; e < E; e++)
            g_pos[e] = atomicAdd(&g_cnt[receivers[e]], 1);
    }
}

__global__ __launch_bounds__(SCAN_BLK)
void scan1_kernel(int N) {
    __shared__ int wsum[32];
    int i = blockIdx.x * SCAN_BLK + threadIdx.x;
    int lane = threadIdx.x & 31, w = threadIdx.x >> 5;
    int v = 0;
    if (i < N) { v = g_cnt[i]; g_cnt[i] = 0; }   // read + re-zero for replay
    int incl = v;
#pragma unroll
    for (int o = 1; o < 32; o <<= 1) {
        int t = __shfl_up_sync(0xffffffffu, incl, o);
        if (lane >= o) incl += t;
    }
    if (lane == 31) wsum[w] = incl;
    __syncthreads();
    if (w == 0) {
        int s = wsum[lane];
#pragma unroll
        for (int o = 1; o < 32; o <<= 1) {
            int t = __shfl_up_sync(0xffffffffu, s, o);
            if (lane >= o) s += t;
        }
        wsum[lane] = s;
    }
    __syncthreads();
    int woff = (w > 0) ? wsum[w - 1] : 0;
    if (i < N) g_row[i] = woff + incl - v;       // exclusive (block-local)
    if (threadIdx.x == SCAN_BLK - 1) g_bsum[blockIdx.x] = woff + incl;
}

__global__ void scan23_kernel(int N, int E) {
    __shared__ int soff;
    int i = blockIdx.x * blockDim.x + threadIdx.x;
    int g = (int)((blockIdx.x * blockDim.x) / SCAN_BLK);
    if (threadIdx.x < 32) {
        int lane = threadIdx.x;
        int acc = 0;
        for (int b = lane; b < g; b += 32) acc += g_bsum[b];
#pragma unroll
        for (int o = 16; o > 0; o >>= 1) acc += __shfl_xor_sync(0xffffffffu, acc, o);
        if (lane == 0) soff = acc;
    }
    __syncthreads();
    if (i < N) g_row[i] += soff;
    if (i == 0) g_row[N] = E;
}

__global__ void fill_kernel(const int* __restrict__ senders,
                            const int* __restrict__ receivers, int E) {
    int t = blockIdx.x * blockDim.x + threadIdx.x;
    int e0 = t * 4;
    if (e0 + 3 < E) {
        int4 r = *reinterpret_cast<const int4*>(&receivers[e0]);
        int4 s = *reinterpret_cast<const int4*>(&senders[e0]);
        int4 p = *reinterpret_cast<const int4*>(&g_pos[e0]);
        g_csr[g_row[r.x] + p.x] = s.x;
        g_csr[g_row[r.y] + p.y] = s.y;
        g_csr[g_row[r.z] + p.z] = s.z;
        g_csr[g_row[r.w] + p.w] = s.w;
    } else {
        for (int e = e0; e < E; e++)
            g_csr[g_row[receivers[e]] + g_pos[e]] = senders[e];
    }
}

// ---------------------------------------------------------------------------
// Fused node kernel: 16 lanes/node (2 nodes/warp), 3-stage software pipeline:
//   stage A: csr loads for block b+2 (affine indices)
//   stage B: es/nt loads for block b+1 (csr ready 1 iter ago)
//   stage C: accumulate block b       (es/nt ready 1 iter ago)
// Tail handled by clamped indices + zeroed weights.
// ---------------------------------------------------------------------------
__device__ __forceinline__ void accum8(float2* a, uint4 u, float w) {
    float2 p0 = __half22float2(*reinterpret_cast<__half2*>(&u.x));
    float2 p1 = __half22float2(*reinterpret_cast<__half2*>(&u.y));
    float2 p2 = __half22float2(*reinterpret_cast<__half2*>(&u.z));
    float2 p3 = __half22float2(*reinterpret_cast<__half2*>(&u.w));
    a[0].x += w * p0.x; a[0].y += w * p0.y;
    a[1].x += w * p1.x; a[1].y += w * p1.y;
    a[2].x += w * p2.x; a[2].y += w * p2.y;
    a[3].x += w * p3.x; a[3].y += w * p3.y;
}

__global__ __launch_bounds__(256)
void node_accum_kernel(float* __restrict__ out, int N) {
    int warp = (blockIdx.x * blockDim.x + threadIdx.x) >> 5;
    int lane = threadIdx.x & 31;
    int node = warp * 2 + (lane >> 4);
    int sl = lane & 15;
    if (node >= N) return;

    const int start = g_row[node];
    const int end   = g_row[node + 1];
    float* outp = out + (size_t)node * DIM + sl * 8;

    if (start == end) {
        *reinterpret_cast<float4*>(outp)     = make_float4(0.f, 0.f, 0.f, 0.f);
        *reinterpret_cast<float4*>(outp + 4) = make_float4(0.f, 0.f, 0.f, 0.f);
        return;
    }

    const int h2 = sl >> 1;
    const __half* ntb = g_nth;
    float2 acc[4];
    acc[0] = acc[1] = acc[2] = acc[3] = make_float2(0.f, 0.f);
    float denom = 0.0f;

    const int nb = (end - start + 3) >> 2;

    // csr loads for block b (clamped to block base for tail)
    auto ld_csr = [&](int b, int* s) {
        int jb = start + b * 4;
        int c = end - jb;
#pragma unroll
        for (int k = 0; k < 4; k++) {
            int jj = jb + (k < c ? k : 0);
            s[k] = __ldg(&g_csr[jj]);
        }
    };
    // es/nt loads for block b; zero weights past end
    auto ld_data = [&](int b, const int* s, float* w, uint4* u) {
        int c = end - (start + b * 4);
#pragma unroll
        for (int k = 0; k < 4; k++) {
            w[k] = g_es[(size_t)s[k] * HEADS + h2];
            u[k] = *reinterpret_cast<const uint4*>(&ntb[(size_t)s[k] * DIM + sl * 8]);
        }
#pragma unroll
        for (int k = 0; k < 4; k++)
            if (k >= c) w[k] = 0.0f;
    };

    // pipeline prologue
    int   sN[4];                 // csr of block b+1
    float wC[4]; uint4 uC[4];    // es/nt of block b
    {
        int s0[4];
        ld_csr(0, s0);
        if (nb > 1) ld_csr(1, sN);
        ld_data(0, s0, wC, uC);
    }

    for (int b = 0; b < nb; b++) {
        int   s2[4];
        float wN[4]; uint4 uN[4];
        if (b + 2 < nb) ld_csr(b + 2, s2);          // stage A
        if (b + 1 < nb) ld_data(b + 1, sN, wN, uN); // stage B
        // stage C: consume block b
#pragma unroll
        for (int k = 0; k < 4; k++) {
            accum8(acc, uC[k], wC[k]);
            denom += wC[k];
        }
        // rotate
        if (b + 1 < nb) {
#pragma unroll
            for (int k = 0; k < 4; k++) { wC[k] = wN[k]; uC[k] = uN[k]; }
        }
        if (b + 2 < nb) {
#pragma unroll
            for (int k = 0; k < 4; k++) sN[k] = s2[k];
        }
    }

    float inv = 1.0f / denom;
    *reinterpret_cast<float4*>(outp) =
        make_float4(acc[0].x * inv, acc[0].y * inv, acc[1].x * inv, acc[1].y * inv);
    *reinterpret_cast<float4*>(outp + 4) =
        make_float4(acc[2].x * inv, acc[2].y * inv, acc[3].x * inv, acc[3].y * inv);
}

// ---------------------------------------------------------------------------
extern "C" void kernel_launch(void* const* d_in, const int* in_sizes, int n_in,
                              void* d_out, int out_size) {
    const float* nodes     = (const float*)d_in[0];
    const int*   senders   = (const int*)d_in[1];
    const int*   receivers = (const int*)d_in[2];
    const float* W         = (const float*)d_in[3];
    const float* b         = (const float*)d_in[4];
    const float* attn_w    = (const float*)d_in[5];
    // attn_b (d_in[6]) cancels in the segment softmax

    const int N = in_sizes[0] / DIM;
    const int E = in_sizes[1];
    float* out = (float*)d_out;

    const int nb = (N + SCAN_BLK - 1) / SCAN_BLK;
    const int tiles = (N + 127) / 128;
    const int e4blocks = ((E + 3) / 4 + 255) / 256;

    static cudaStream_t s_side = nullptr;
    static cudaEvent_t ev_fork = nullptr, ev_join = nullptr;
    if (!s_side) {
        cudaStreamCreateWithFlags(&s_side, cudaStreamNonBlocking);
        cudaEventCreateWithFlags(&ev_fork, cudaEventDisableTiming);
        cudaEventCreateWithFlags(&ev_join, cudaEventDisableTiming);
        cudaFuncSetAttribute(gemm_mma_kernel,
                             cudaFuncAttributeMaxDynamicSharedMemorySize, SM_TOTAL);
    }

    // fork: CSR build on side stream, GEMM chain on main stream
    cudaEventRecord(ev_fork, 0);
    cudaStreamWaitEvent(s_side, ev_fork, 0);

    count_kernel<<<e4blocks, 256, 0, s_side>>>(receivers, E);
    scan1_kernel<<<nb, SCAN_BLK, 0, s_side>>>(N);
    scan23_kernel<<<(N + 255) / 256, 256, 0, s_side>>>(N, E);
    fill_kernel<<<e4blocks, 256, 0, s_side>>>(senders, receivers, E);

    prep_w_kernel<<<(DIM * DIM + 255) / 256, 256>>>(W);
    gemm_mma_kernel<<<tiles, 256, SM_TOTAL>>>(nodes, b, attn_w, N);

    // join
    cudaEventRecord(ev_join, s_side);
    cudaStreamWaitEvent(0, ev_join, 0);

    node_accum_kernel<<<(N * 16 + 255) / 256, 256>>>(out, N);
}

// round 13
// speedup vs baseline: 1.3440x; 1.3440x over previous
#include <cuda_runtime.h>
#include <cuda_bf16.h>
#include <cuda_fp16.h>
#include <cstdint>
#include <math.h>

#define DIM      128
#define HEADS    8
#define NMAX     100000
#define EMAX     1600000
#define SCAN_BLK 1024
#define MAX_BLKS ((NMAX + SCAN_BLK - 1) / SCAN_BLK + 2)

// ---------------- device scratch (allocation-free rule) ----------------
__device__ __half g_nth[(size_t)NMAX * DIM]; // transformed node features (fp16)
__device__ float g_es[(size_t)NMAX * HEADS]; // exp(sender score)
__device__ int   g_cnt[NMAX];                // in-degree counts (kept zeroed)
__device__ int   g_row[NMAX + 1];            // CSR row offsets
__device__ int   g_pos[EMAX];                // per-edge slot within its segment
__device__ int   g_csr[EMAX];                // CSR payload: sender ids
__device__ int   g_bsum[MAX_BLKS];           // scan block sums
// W in per-lane mma B-fragment order: [colTile(16)][ks(8)][lane(32)] of
// uint4 {bh0, bh1, bl0, bl1} (bf16x2 each). 64 KB, L1/L2-hot.
__device__ __align__(16) uint4 g_Bfrag[16 * 8 * 32];

__device__ __forceinline__ float lrelu(float x) { return x > 0.0f ? x : 0.2f * x; }

__device__ __forceinline__ uint32_t smem_u32(const void* p) {
    uint32_t a;
    asm("{ .reg .u64 t; cvta.to.shared.u64 t, %1; cvt.u32.u64 %0, t; }" : "=r"(a) : "l"(p));
    return a;
}

// swizzled byte offset inside a [rows][128 bf16] tile (256B rows)
__device__ __forceinline__ uint32_t toff(int row, int k) {
    return (uint32_t)(row * 256 + ((((k >> 3) ^ (row & 7)) & 15) << 4) + ((k & 7) << 1));
}

#define LDSM4(r, addr) asm volatile( \
    "ldmatrix.sync.aligned.m8n8.x4.shared.b16 {%0,%1,%2,%3}, [%4];" \
    : "=r"((r)[0]), "=r"((r)[1]), "=r"((r)[2]), "=r"((r)[3]) : "r"(addr))
#define MMA(c, a, b) asm volatile( \
    "mma.sync.aligned.m16n8k16.row.col.f32.bf16.bf16.f32 " \
    "{%0,%1,%2,%3},{%4,%5,%6,%7},{%8,%9},{%0,%1,%2,%3};" \
    : "+f"((c)[0]), "+f"((c)[1]), "+f"((c)[2]), "+f"((c)[3]) \
    : "r"((a)[0]), "r"((a)[1]), "r"((a)[2]), "r"((a)[3]), "r"((b)[0]), "r"((b)[1]))

__device__ __forceinline__ uint32_t pack_bf16x2(float a0, float a1) {
    __nv_bfloat162 v = __halves2bfloat162(__float2bfloat16(a0), __float2bfloat16(a1));
    return *reinterpret_cast<uint32_t*>(&v);
}

// ---------------------------------------------------------------------------
// prep: W (fp32 [k][n]) -> per-lane B fragments (hi/lo bf16 split).
// For mma.m16n8k16 row.col, lane L of colTile ct, k-step ks holds:
//   n  = ct*8 + L/4
//   k0 = ks*16 + (L%4)*2
//   bh0 = {hi(W[k0][n]),   hi(W[k0+1][n])}
//   bh1 = {hi(W[k0+8][n]), hi(W[k0+9][n])}
//   bl0, bl1 analogous with lo = x - bf16(x).
// ---------------------------------------------------------------------------
__global__ void prep_w_kernel(const float* __restrict__ W) {
    int t = blockIdx.x * blockDim.x + threadIdx.x;   // 0..4095
    if (t >= 16 * 8 * 32) return;
    int lane = t & 31;
    int ks = (t >> 5) & 7;
    int ct = t >> 8;
    int n = ct * 8 + (lane >> 2);
    int k0 = ks * 16 + (lane & 3) * 2;

    float x0 = W[(size_t)k0 * DIM + n];
    float x1 = W[(size_t)(k0 + 1) * DIM + n];
    float x2 = W[(size_t)(k0 + 8) * DIM + n];
    float x3 = W[(size_t)(k0 + 9) * DIM + n];

    float h0 = __bfloat162float(__float2bfloat16(x0));
    float h1 = __bfloat162float(__float2bfloat16(x1));
    float h2 = __bfloat162float(__float2bfloat16(x2));
    float h3 = __bfloat162float(__float2bfloat16(x3));

    uint4 f;
    f.x = pack_bf16x2(x0, x1);                 // bh0
    f.y = pack_bf16x2(x2, x3);                 // bh1
    f.z = pack_bf16x2(x0 - h0, x1 - h1);       // bl0
    f.w = pack_bf16x2(x2 - h2, x3 - h3);       // bl1
    g_Bfrag[t] = f;
}

// ---------------------------------------------------------------------------
// GEMM: bf16-split mma.sync, 128-row tiles. A in smem (64KB -> 2 blocks/SM),
// B fragments direct from global (L1-hot). Epilogue: +bias, store nt (fp16),
// fused per-head score -> g_es = exp(score).
// ---------------------------------------------------------------------------
#define SM_AHI 0
#define SM_ALO 32768
#define SM_TOTAL 65536

__global__ __launch_bounds__(256, 2)
void gemm_mma_kernel(const float* __restrict__ A, const float* __restrict__ bias,
                     const float* __restrict__ attn_w, int N) {
    extern __shared__ __align__(1024) char smem[];
    const uint32_t sb = smem_u32(smem);
    const int tid = threadIdx.x;
    const int wid = tid >> 5;
    const int lane = tid & 31;
    const int row0 = blockIdx.x * 128;

    // load A tile (128 x 128 fp32), split hi/lo bf16, store swizzled
    for (int i = 0; i < 16; i++) {
        int idx4 = tid + i * 256;
        int r = idx4 >> 5;
        int c4 = (idx4 & 31) * 4;
        float4 v = make_float4(0.f, 0.f, 0.f, 0.f);
        if (row0 + r < N)
            v = *reinterpret_cast<const float4*>(&A[(size_t)(row0 + r) * DIM + c4]);
        float xs[4] = {v.x, v.y, v.z, v.w};
        __nv_bfloat16 hs[4], ls[4];
#pragma unroll
        for (int j = 0; j < 4; j++) {
            hs[j] = __float2bfloat16(xs[j]);
            ls[j] = __float2bfloat16(xs[j] - __bfloat162float(hs[j]));
        }
        uint32_t so = toff(r, c4);
        *reinterpret_cast<__nv_bfloat162*>(smem + SM_AHI + so)     = __halves2bfloat162(hs[0], hs[1]);
        *reinterpret_cast<__nv_bfloat162*>(smem + SM_AHI + so + 4) = __halves2bfloat162(hs[2], hs[3]);
        *reinterpret_cast<__nv_bfloat162*>(smem + SM_ALO + so)     = __halves2bfloat162(ls[0], ls[1]);
        *reinterpret_cast<__nv_bfloat162*>(smem + SM_ALO + so + 4) = __halves2bfloat162(ls[2], ls[3]);
    }
    __syncthreads();

    const int wm = wid >> 2;
    const int wn = wid & 3;
    const int r_base = wm * 64;
    const int n_base = wn * 32;

    float acc[4][4][4];
#pragma unroll
    for (int mi = 0; mi < 4; mi++)
#pragma unroll
        for (int ni = 0; ni < 4; ni++)
#pragma unroll
            for (int q = 0; q < 4; q++) acc[mi][ni][q] = 0.0f;

    const int L = lane & 15;
#pragma unroll
    for (int ks = 0; ks < 8; ks++) {
        uint32_t ah[4][4], al[4][4];
        const int ka = ks * 16 + (lane >> 4) * 8;
#pragma unroll
        for (int mi = 0; mi < 4; mi++) {
            uint32_t off = toff(r_base + mi * 16 + L, ka);
            LDSM4(ah[mi], sb + SM_AHI + off);
            LDSM4(al[mi], sb + SM_ALO + off);
        }
#pragma unroll
        for (int ni = 0; ni < 4; ni++) {
            uint4 f = __ldg(&g_Bfrag[(((wn * 4 + ni) * 8 + ks) << 5) + lane]);
            uint32_t bh[2] = {f.x, f.y};
            uint32_t bl[2] = {f.z, f.w};
#pragma unroll
            for (int mi = 0; mi < 4; mi++) {
                MMA(acc[mi][ni], ah[mi], bh);
                MMA(acc[mi][ni], ah[mi], bl);
                MMA(acc[mi][ni], al[mi], bh);
            }
        }
    }

    // ---- epilogue ----
    float aw[16];
#pragma unroll
    for (int j = 0; j < 16; j++) aw[j] = __ldg(&attn_w[j]);

    float sp[8][2];
#pragma unroll
    for (int q = 0; q < 8; q++) { sp[q][0] = 0.0f; sp[q][1] = 0.0f; }

#pragma unroll
    for (int ni = 0; ni < 4; ni++) {
        int n0 = n_base + ni * 8 + (lane & 3) * 2;
        float bw0 = __ldg(&bias[n0]), bw1 = __ldg(&bias[n0 + 1]);
        float aw0 = aw[n0 & 15], aw1 = aw[(n0 + 1) & 15];
        int hl = ni >> 1;
#pragma unroll
        for (int mi = 0; mi < 4; mi++) {
            float c0 = acc[mi][ni][0] + bw0, c1 = acc[mi][ni][1] + bw1;
            float c2 = acc[mi][ni][2] + bw0, c3 = acc[mi][ni][3] + bw1;
            int ra = row0 + r_base + mi * 16 + (lane >> 2);
            int rb = ra + 8;
            if (ra < N) *reinterpret_cast<__half2*>(&g_nth[(size_t)ra * DIM + n0]) = __floats2half2_rn(c0, c1);
            if (rb < N) *reinterpret_cast<__half2*>(&g_nth[(size_t)rb * DIM + n0]) = __floats2half2_rn(c2, c3);
            sp[mi * 2 + 0][hl] += lrelu(c0) * aw0 + lrelu(c1) * aw1;
            sp[mi * 2 + 1][hl] += lrelu(c2) * aw0 + lrelu(c3) * aw1;
        }
    }
#pragma unroll
    for (int slot = 0; slot < 8; slot++)
#pragma unroll
        for (int hl = 0; hl < 2; hl++) {
            float v = sp[slot][hl];
            v += __shfl_xor_sync(0xffffffffu, v, 1);
            v += __shfl_xor_sync(0xffffffffu, v, 2);
            if ((lane & 3) == 0) {
                int row = row0 + r_base + (slot >> 1) * 16 + (slot & 1) * 8 + (lane >> 2);
                if (row < N) g_es[(size_t)row * HEADS + wn * 2 + hl] = __expf(v);
            }
        }
}

// ---------------------------------------------------------------------------
// CSR build (side stream): count (+slot record) -> scan1 -> scan23 -> fill
// ---------------------------------------------------------------------------
__global__ void count_kernel(const int* __restrict__ receivers, int E) {
    int t = blockIdx.x * blockDim.x + threadIdx.x;
    int e0 = t * 4;
    if (e0 + 3 < E) {
        int4 r = *reinterpret_cast<const int4*>(&receivers[e0]);
        int4 p;
        p.x = atomicAdd(&g_cnt[r.x], 1);
        p.y = atomicAdd(&g_cnt[r.y], 1);
        p.z = atomicAdd(&g_cnt[r.z], 1);
        p.w = atomicAdd(&g_cnt[r.w], 1);
        *reinterpret_cast<int4*>(&g_pos[e0]) = p;
    } else {
        for (int e = e0; e < E; e++)
            g_pos[e] = atomicAdd(&g_cnt[receivers[e]], 1);
    }
}

__global__ __launch_bounds__(SCAN_BLK)
void scan1_kernel(int N) {
    __shared__ int wsum[32];
    int i = blockIdx.x * SCAN_BLK + threadIdx.x;
    int lane = threadIdx.x & 31, w = threadIdx.x >> 5;
    int v = 0;
    if (i < N) { v = g_cnt[i]; g_cnt[i] = 0; }   // read + re-zero for replay
    int incl = v;
#pragma unroll
    for (int o = 1; o < 32; o <<= 1) {
        int t = __shfl_up_sync(0xffffffffu, incl, o);
        if (lane >= o) incl += t;
    }
    if (lane == 31) wsum[w] = incl;
    __syncthreads();
    if (w == 0) {
        int s = wsum[lane];
#pragma unroll
        for (int o = 1; o < 32; o <<= 1) {
            int t = __shfl_up_sync(0xffffffffu, s, o);
            if (lane >= o) s += t;
        }
        wsum[lane] = s;
    }
    __syncthreads();
    int woff = (w > 0) ? wsum[w - 1] : 0;
    if (i < N) g_row[i] = woff + incl - v;       // exclusive (block-local)
    if (threadIdx.x == SCAN_BLK - 1) g_bsum[blockIdx.x] = woff + incl;
}

__global__ void scan23_kernel(int N, int E) {
    __shared__ int soff;
    int i = blockIdx.x * blockDim.x + threadIdx.x;
    int g = (int)((blockIdx.x * blockDim.x) / SCAN_BLK);
    if (threadIdx.x < 32) {
        int lane = threadIdx.x;
        int acc = 0;
        for (int b = lane; b < g; b += 32) acc += g_bsum[b];
#pragma unroll
        for (int o = 16; o > 0; o >>= 1) acc += __shfl_xor_sync(0xffffffffu, acc, o);
        if (lane == 0) soff = acc;
    }
    __syncthreads();
    if (i < N) g_row[i] += soff;
    if (i == 0) g_row[N] = E;
}

__global__ void fill_kernel(const int* __restrict__ senders,
                            const int* __restrict__ receivers, int E) {
    int t = blockIdx.x * blockDim.x + threadIdx.x;
    int e0 = t * 4;
    if (e0 + 3 < E) {
        int4 r = *reinterpret_cast<const int4*>(&receivers[e0]);
        int4 s = *reinterpret_cast<const int4*>(&senders[e0]);
        int4 p = *reinterpret_cast<const int4*>(&g_pos[e0]);
        g_csr[g_row[r.x] + p.x] = s.x;
        g_csr[g_row[r.y] + p.y] = s.y;
        g_csr[g_row[r.z] + p.z] = s.z;
        g_csr[g_row[r.w] + p.w] = s.w;
    } else {
        for (int e = e0; e < E; e++)
            g_csr[g_row[receivers[e]] + g_pos[e]] = senders[e];
    }
}

// ---------------------------------------------------------------------------
// Fused node kernel (R11-proven): 16 lanes/node (2 nodes/warp),
// 4-edge unroll + scalar tail.
// ---------------------------------------------------------------------------
__device__ __forceinline__ void accum8(float2* a, uint4 u, float w) {
    float2 p0 = __half22float2(*reinterpret_cast<__half2*>(&u.x));
    float2 p1 = __half22float2(*reinterpret_cast<__half2*>(&u.y));
    float2 p2 = __half22float2(*reinterpret_cast<__half2*>(&u.z));
    float2 p3 = __half22float2(*reinterpret_cast<__half2*>(&u.w));
    a[0].x += w * p0.x; a[0].y += w * p0.y;
    a[1].x += w * p1.x; a[1].y += w * p1.y;
    a[2].x += w * p2.x; a[2].y += w * p2.y;
    a[3].x += w * p3.x; a[3].y += w * p3.y;
}

__global__ __launch_bounds__(256)
void node_accum_kernel(float* __restrict__ out, int N) {
    int warp = (blockIdx.x * blockDim.x + threadIdx.x) >> 5;
    int lane = threadIdx.x & 31;
    int node = warp * 2 + (lane >> 4);
    int sl = lane & 15;
    if (node >= N) return;

    int start = g_row[node];
    int end   = g_row[node + 1];
    float* outp = out + (size_t)node * DIM + sl * 8;

    if (start == end) {
        *reinterpret_cast<float4*>(outp)     = make_float4(0.f, 0.f, 0.f, 0.f);
        *reinterpret_cast<float4*>(outp + 4) = make_float4(0.f, 0.f, 0.f, 0.f);
        return;
    }

    const int h2 = sl >> 1;
    const __half* ntb = g_nth;
    float2 acc[4];
    acc[0] = acc[1] = acc[2] = acc[3] = make_float2(0.f, 0.f);
    float denom = 0.0f;

    int j = start;
    for (; j + 3 < end; j += 4) {
        int s0 = __ldg(&g_csr[j]);
        int s1 = __ldg(&g_csr[j + 1]);
        int s2 = __ldg(&g_csr[j + 2]);
        int s3 = __ldg(&g_csr[j + 3]);
        float w0 = g_es[(size_t)s0 * HEADS + h2];
        float w1 = g_es[(size_t)s1 * HEADS + h2];
        float w2 = g_es[(size_t)s2 * HEADS + h2];
        float w3 = g_es[(size_t)s3 * HEADS + h2];
        uint4 u0 = *reinterpret_cast<const uint4*>(&ntb[(size_t)s0 * DIM + sl * 8]);
        uint4 u1 = *reinterpret_cast<const uint4*>(&ntb[(size_t)s1 * DIM + sl * 8]);
        uint4 u2 = *reinterpret_cast<const uint4*>(&ntb[(size_t)s2 * DIM + sl * 8]);
        uint4 u3 = *reinterpret_cast<const uint4*>(&ntb[(size_t)s3 * DIM + sl * 8]);
        accum8(acc, u0, w0);
        accum8(acc, u1, w1);
        accum8(acc, u2, w2);
        accum8(acc, u3, w3);
        denom += (w0 + w1) + (w2 + w3);
    }
    for (; j < end; j++) {
        int s0 = __ldg(&g_csr[j]);
        float w0 = g_es[(size_t)s0 * HEADS + h2];
        uint4 u0 = *reinterpret_cast<const uint4*>(&ntb[(size_t)s0 * DIM + sl * 8]);
        accum8(acc, u0, w0);
        denom += w0;
    }

    float inv = 1.0f / denom;
    *reinterpret_cast<float4*>(outp) =
        make_float4(acc[0].x * inv, acc[0].y * inv, acc[1].x * inv, acc[1].y * inv);
    *reinterpret_cast<float4*>(outp + 4) =
        make_float4(acc[2].x * inv, acc[2].y * inv, acc[3].x * inv, acc[3].y * inv);
}

// ---------------------------------------------------------------------------
extern "C" void kernel_launch(void* const* d_in, const int* in_sizes, int n_in,
                              void* d_out, int out_size) {
    const float* nodes     = (const float*)d_in[0];
    const int*   senders   = (const int*)d_in[1];
    const int*   receivers = (const int*)d_in[2];
    const float* W         = (const float*)d_in[3];
    const float* b         = (const float*)d_in[4];
    const float* attn_w    = (const float*)d_in[5];
    // attn_b (d_in[6]) cancels in the segment softmax

    const int N = in_sizes[0] / DIM;
    const int E = in_sizes[1];
    float* out = (float*)d_out;

    const int nb = (N + SCAN_BLK - 1) / SCAN_BLK;
    const int tiles = (N + 127) / 128;
    const int e4blocks = ((E + 3) / 4 + 255) / 256;

    static cudaStream_t s_side = nullptr;
    static cudaEvent_t ev_fork = nullptr, ev_join = nullptr;
    if (!s_side) {
        cudaStreamCreateWithFlags(&s_side, cudaStreamNonBlocking);
        cudaEventCreateWithFlags(&ev_fork, cudaEventDisableTiming);
        cudaEventCreateWithFlags(&ev_join, cudaEventDisableTiming);
        cudaFuncSetAttribute(gemm_mma_kernel,
                             cudaFuncAttributeMaxDynamicSharedMemorySize, SM_TOTAL);
    }

    // fork: CSR build on side stream, GEMM chain on main stream
    cudaEventRecord(ev_fork, 0);
    cudaStreamWaitEvent(s_side, ev_fork, 0);

    count_kernel<<<e4blocks, 256, 0, s_side>>>(receivers, E);
    scan1_kernel<<<nb, SCAN_BLK, 0, s_side>>>(N);
    scan23_kernel<<<(N + 255) / 256, 256, 0, s_side>>>(N, E);
    fill_kernel<<<e4blocks, 256, 0, s_side>>>(senders, receivers, E);

    prep_w_kernel<<<16, 256>>>(W);
    gemm_mma_kernel<<<tiles, 256, SM_TOTAL>>>(nodes, b, attn_w, N);

    // join
    cudaEventRecord(ev_join, s_side);
    cudaStreamWaitEvent(0, ev_join, 0);

    node_accum_kernel<<<(N * 16 + 255) / 256, 256>>>(out, N);
}